// round 2
// baseline (speedup 1.0000x reference)
#include <cuda_runtime.h>
#include <math.h>

#define BB 16
#define FF 2048
#define SS 512
#define DD 256
#define DH 512
#define NSEG (BB*SS)      // 8192
#define NEDGE (BB*FF)     // 32768
#define DLAT 512

// ---- scratch (static __device__ arrays; no allocations allowed) ----
__device__ float g_Pa[SS*DH];        // pos_emb @ W1[0:256]      1 MB
__device__ float g_Pc[SS*DH];        // pos_emb @ W1[512:768]    1 MB
__device__ float g_Eb[8*DH];         // pred_emb @ W1[256:512]
__device__ float g_Rc[8*DH];         // role_emb @ W1[512:768]
__device__ float g_H[NSEG*DH];       // per-node hidden sums    16 MB
__device__ float g_agg[NSEG*DD];     // H @ W2                   8 MB
__device__ float g_pooled[BB*DD];
__device__ int   g_cnt[NSEG];
__device__ int   g_off[NSEG];
__device__ int   g_run[NSEG];
__device__ unsigned g_perm[2*NEDGE];

__device__ __forceinline__ float gelu_f(float x){
    return 0.5f*x*(1.0f + erff(x*0.70710678118654752440f));
}

// ---- zero per-launch state ----
__global__ void k_zero(){
    int i = blockIdx.x*256 + threadIdx.x;
    if (i < NSEG)   g_cnt[i] = 0;
    if (i < BB*DD)  g_pooled[i] = 0.f;
}

// ---- CSR build: count messages per destination node ----
__global__ void k_count(const int* __restrict__ a0, const int* __restrict__ a1,
                        const int* __restrict__ pidx){
    int e = blockIdx.x*256 + threadIdx.x;
    if (e >= NEDGE) return;
    int b = e / FF;
    int v0 = a0[e], v1 = a1[e], p = pidx[e];
    bool role = (p == 1);
    int dstf = role ? v0 : v1;
    atomicAdd(&g_cnt[b*SS + dstf], 1);
    if (!role && p != 0) atomicAdd(&g_cnt[b*SS + v0], 1);
}

// ---- exclusive prefix sum over 8192 counts (single block) ----
__global__ void k_scan(){
    __shared__ int wsum[32];
    int tid = threadIdx.x;            // 1024 threads, 8 elems each
    int base = tid*8;
    int v[8]; int s = 0;
    #pragma unroll
    for (int i=0;i<8;i++){ v[i]=s; s += g_cnt[base+i]; }
    int lane = tid & 31, warp = tid >> 5;
    int x = s;
    #pragma unroll
    for (int o=1;o<32;o<<=1){ int y=__shfl_up_sync(0xffffffffu,x,o); if(lane>=o) x+=y; }
    if (lane==31) wsum[warp]=x;
    __syncthreads();
    if (warp==0){
        int w = wsum[lane];
        #pragma unroll
        for (int o=1;o<32;o<<=1){ int y=__shfl_up_sync(0xffffffffu,w,o); if(lane>=o) w+=y; }
        wsum[lane]=w;
    }
    __syncthreads();
    int excl = x - s + (warp ? wsum[warp-1] : 0);
    #pragma unroll
    for (int i=0;i<8;i++){ int o = excl+v[i]; g_off[base+i]=o; g_run[base+i]=o; }
}

// ---- place message descriptors into CSR slots ----
// desc: bits[0:10)=row for P_a, [10:20)=row for P_c (or R_c), [20:23)=pred, [23]=use R_c
__global__ void k_place(const int* __restrict__ a0, const int* __restrict__ a1,
                        const int* __restrict__ pidx, const int* __restrict__ ridx){
    int e = blockIdx.x*256 + threadIdx.x;
    if (e >= NEDGE) return;
    int b = e / FF;
    int v0=a0[e], v1=a1[e], p=pidx[e];
    bool role = (p==1);
    unsigned descf; int dstf;
    if (role){ dstf=v0; descf=(unsigned)v0 | ((unsigned)(ridx[e]+1)<<10) | ((unsigned)p<<20) | (1u<<23); }
    else     { dstf=v1; descf=(unsigned)v0 | ((unsigned)v1<<10)          | ((unsigned)p<<20); }
    int slot = atomicAdd(&g_run[b*SS+dstf],1);
    g_perm[slot]=descf;
    if (!role && p!=0){
        unsigned descb = (unsigned)v1 | ((unsigned)v0<<10) | ((unsigned)p<<20);
        slot = atomicAdd(&g_run[b*SS+v0],1);
        g_perm[slot]=descb;
    }
}

// ---- tiled fp32 GEMM: C[M,N] = A[M,K] @ B[K,N], row-major, M%64==N%64==0, K%16==0 ----
__global__ void k_gemm(const float* __restrict__ A, const float* __restrict__ Bm,
                       float* __restrict__ C, int M, int N, int K){
    __shared__ float As[16][68];
    __shared__ float Bs[16][64];
    int tid = threadIdx.x;                 // 256
    int bm = blockIdx.y*64, bn = blockIdx.x*64;
    int tx = tid & 15, ty = tid >> 4;      // 16x16, each thread 4x4
    int la_k = tid & 15, la_m = (tid >> 4)*4;
    int lb_n = tid & 63, lb_k = (tid >> 6)*4;
    float acc[4][4] = {};
    for (int k0=0;k0<K;k0+=16){
        #pragma unroll
        for (int i=0;i<4;i++) As[la_k][la_m+i] = A[(size_t)(bm+la_m+i)*K + k0 + la_k];
        #pragma unroll
        for (int i=0;i<4;i++) Bs[lb_k+i][lb_n] = Bm[(size_t)(k0+lb_k+i)*N + bn + lb_n];
        __syncthreads();
        #pragma unroll
        for (int k=0;k<16;k++){
            float a[4], bv[4];
            #pragma unroll
            for (int i=0;i<4;i++) a[i]=As[k][ty*4+i];
            #pragma unroll
            for (int j=0;j<4;j++) bv[j]=Bs[k][tx*4+j];
            #pragma unroll
            for (int i=0;i<4;i++)
                #pragma unroll
                for (int j=0;j<4;j++) acc[i][j] += a[i]*bv[j];
        }
        __syncthreads();
    }
    #pragma unroll
    for (int i=0;i<4;i++)
        #pragma unroll
        for (int j=0;j<4;j++)
            C[(size_t)(bm+ty*4+i)*N + bn+tx*4+j] = acc[i][j];
}

// ---- tiny GEMM for 8-row tables: C[8,512] = A[8,256] @ W[256,512] ----
__global__ void k_smallmm(const float* __restrict__ A, const float* __restrict__ W,
                          float* __restrict__ C){
    __shared__ float a[DD];
    int r = blockIdx.x, j = threadIdx.x;   // 512 threads
    if (j < DD) a[j] = A[r*DD + j];
    __syncthreads();
    float s = 0.f;
    for (int k=0;k<DD;k++) s += a[k]*W[k*DH + j];
    C[r*DH + j] = s;
}

// ---- per-node gather: H[node] = sum over its messages of gelu(Pa+T+Eb+b1) ----
__global__ void k_gather(const float* __restrict__ b1){
    int node = blockIdx.x;                 // 8192 nodes
    int tid = threadIdx.x;                 // 128 threads, 4 floats each
    int start = g_off[node];
    int cnt = g_cnt[node];
    float4 b1v = reinterpret_cast<const float4*>(b1)[tid];
    float4 acc = make_float4(0.f,0.f,0.f,0.f);
    const float4* PA = reinterpret_cast<const float4*>(g_Pa);
    const float4* PC = reinterpret_cast<const float4*>(g_Pc);
    const float4* EB = reinterpret_cast<const float4*>(g_Eb);
    const float4* RC = reinterpret_cast<const float4*>(g_Rc);
    for (int m=0;m<cnt;m++){
        unsigned d = g_perm[start+m];
        int iA = d & 1023, iC = (d>>10)&1023, p = (d>>20)&7;
        const float4* T = (d & (1u<<23)) ? RC : PC;
        float4 a = PA[iA*128 + tid];
        float4 c = T [iC*128 + tid];
        float4 e = EB[p *128 + tid];
        acc.x += gelu_f(a.x+c.x+e.x+b1v.x);
        acc.y += gelu_f(a.y+c.y+e.y+b1v.y);
        acc.z += gelu_f(a.z+c.z+e.z+b1v.z);
        acc.w += gelu_f(a.w+c.w+e.w+b1v.w);
    }
    reinterpret_cast<float4*>(g_H)[node*128 + tid] = acc;
}

// ---- x = pos + agg + cnt*b2 ; layernorm ; accumulate pooled sums ----
__global__ void k_ln(const float* __restrict__ pos, const float* __restrict__ b2,
                     const float* __restrict__ lng, const float* __restrict__ lnb){
    __shared__ float sp[DD];
    int bIdx = blockIdx.y;                 // batch
    int r0 = blockIdx.x*64;                // 64 rows per block
    int tid = threadIdx.x;                 // 256 = 8 warps
    int warp = tid>>5, lane = tid&31;
    float accp[8];
    #pragma unroll
    for (int i=0;i<8;i++) accp[i]=0.f;
    for (int rr=warp; rr<64; rr+=8){
        int s = r0+rr;
        int seg = bIdx*SS + s;
        float cntf = (float)g_cnt[seg];
        float x[8]; float sum=0.f;
        #pragma unroll
        for (int i=0;i<8;i++){
            int j = lane + 32*i;
            x[i] = pos[s*DD+j] + g_agg[(size_t)seg*DD+j] + cntf*b2[j];
            sum += x[i];
        }
        #pragma unroll
        for (int o=16;o;o>>=1) sum += __shfl_xor_sync(0xffffffffu,sum,o);
        float mu = sum*(1.0f/DD);
        float vs=0.f;
        #pragma unroll
        for (int i=0;i<8;i++){ float d2 = x[i]-mu; vs += d2*d2; }
        #pragma unroll
        for (int o=16;o;o>>=1) vs += __shfl_xor_sync(0xffffffffu,vs,o);
        float inv = rsqrtf(vs*(1.0f/DD)+1e-5f);
        #pragma unroll
        for (int i=0;i<8;i++){
            int j = lane+32*i;
            accp[i] += (x[i]-mu)*inv*lng[j] + lnb[j];
        }
    }
    if (tid < DD) sp[tid]=0.f;
    __syncthreads();
    #pragma unroll
    for (int i=0;i<8;i++) atomicAdd(&sp[lane+32*i], accp[i]);
    __syncthreads();
    if (tid < DD) atomicAdd(&g_pooled[bIdx*DD+tid], sp[tid]);
}

// ---- final tiny MLP: latent = gelu(pooled@Wl1+bl1)@Wl2+bl2 ----
__global__ void k_final(const float* __restrict__ Wl1, const float* __restrict__ bl1,
                        const float* __restrict__ Wl2, const float* __restrict__ bl2,
                        float* __restrict__ out){
    __shared__ float pp[DD];
    __shared__ float hh[DLAT];
    int b = blockIdx.x, j = threadIdx.x;   // 512 threads
    if (j < DD) pp[j] = g_pooled[b*DD+j]*(1.0f/SS);
    __syncthreads();
    float s = bl1[j];
    for (int k=0;k<DD;k++) s += pp[k]*Wl1[k*DLAT+j];
    hh[j] = gelu_f(s);
    __syncthreads();
    float o = bl2[j];
    for (int k=0;k<DLAT;k++) o += hh[k]*Wl2[k*DLAT+j];
    out[b*DLAT+j] = o;
}

extern "C" void kernel_launch(void* const* d_in, const int* in_sizes, int n_in,
                              void* d_out, int out_size){
    const int*   a0   = (const int*)d_in[0];
    const int*   a1   = (const int*)d_in[1];
    const int*   pidx = (const int*)d_in[2];
    const int*   ridx = (const int*)d_in[3];
    // d_in[4] = seq_len (compile-time constant SS=512)
    const float* pos  = (const float*)d_in[5];
    const float* pre  = (const float*)d_in[6];
    const float* rol  = (const float*)d_in[7];
    const float* W1   = (const float*)d_in[8];
    const float* b1   = (const float*)d_in[9];
    const float* W2   = (const float*)d_in[10];
    const float* b2   = (const float*)d_in[11];
    const float* lng  = (const float*)d_in[12];
    const float* lnb  = (const float*)d_in[13];
    const float* Wl1  = (const float*)d_in[14];
    const float* bl1  = (const float*)d_in[15];
    const float* Wl2  = (const float*)d_in[16];
    const float* bl2  = (const float*)d_in[17];
    float* out = (float*)d_out;

    float *pPa, *pPc, *pEb, *pRc, *pH, *pAgg;
    cudaGetSymbolAddress((void**)&pPa,  g_Pa);
    cudaGetSymbolAddress((void**)&pPc,  g_Pc);
    cudaGetSymbolAddress((void**)&pEb,  g_Eb);
    cudaGetSymbolAddress((void**)&pRc,  g_Rc);
    cudaGetSymbolAddress((void**)&pH,   g_H);
    cudaGetSymbolAddress((void**)&pAgg, g_agg);

    k_zero<<<32,256>>>();
    k_count<<<NEDGE/256,256>>>(a0,a1,pidx);
    k_scan<<<1,1024>>>();
    k_place<<<NEDGE/256,256>>>(a0,a1,pidx,ridx);

    // precompute lookup tables: first-layer GEMM folded into embeddings
    k_gemm<<<dim3(DH/64, SS/64),256>>>(pos, W1,              pPa, SS, DH, DD);
    k_gemm<<<dim3(DH/64, SS/64),256>>>(pos, W1 + 2*DD*DH,    pPc, SS, DH, DD);
    k_smallmm<<<8,512>>>(pre, W1 + DD*DH,   pEb);
    k_smallmm<<<8,512>>>(rol, W1 + 2*DD*DH, pRc);

    // per-node hidden accumulation (atomic-free gather)
    k_gather<<<NSEG,128>>>(b1);

    // agg = H @ W2
    k_gemm<<<dim3(DD/64, NSEG/64),256>>>(pH, W2, pAgg, NSEG, DD, DH);

    // layernorm + pooling, then final MLP
    k_ln<<<dim3(SS/64,BB),256>>>(pos, b2, lng, lnb);
    k_final<<<BB,512>>>(Wl1,bl1,Wl2,bl2,out);
}

// round 4
// speedup vs baseline: 1.1390x; 1.1390x over previous
#include <cuda_runtime.h>
#include <math.h>

#define BB 16
#define FF 2048
#define SS 512
#define DD 256
#define DH 512
#define NSEG (BB*SS)      // 8192
#define NEDGE (BB*FF)     // 32768
#define DLAT 512

typedef unsigned long long ull;

// ---- scratch (static __device__ arrays; no allocations allowed) ----
__device__ __align__(16) float g_P[2*SS*DH];     // [0]=pos@W1a, [1]=pos@W1c  (2 MB)
__device__ __align__(16) float g_Eb[8*DH];       // pred_emb @ W1b
__device__ __align__(16) float g_Rc[8*DH];       // role_emb @ W1c
__device__ __align__(16) float g_H[NSEG*DH];     // per-node hidden sums (16 MB)
__device__ __align__(16) float g_agg[NSEG*DD];   // H @ W2 (8 MB)
__device__ float g_pooled[BB*DD];
__device__ __align__(16) int g_cnt[NSEG];
__device__ int   g_off[NSEG];
__device__ int   g_run[NSEG];
__device__ unsigned g_perm[2*NEDGE];

__device__ __forceinline__ float gelu_f(float x){
    return 0.5f*x*(1.0f + erff(x*0.70710678118654752440f));
}

__device__ __forceinline__ void ffma2(ull &d, ull a, ull b){
    asm("fma.rn.f32x2 %0, %1, %2, %0;" : "+l"(d) : "l"(a), "l"(b));
}
__device__ __forceinline__ ull pack2(float x){
    ull r; asm("mov.b64 %0, {%1, %1};" : "=l"(r) : "f"(x)); return r;
}
__device__ __forceinline__ void unpack2(float &lo, float &hi, ull v){
    asm("mov.b64 {%0, %1}, %2;" : "=f"(lo), "=f"(hi) : "l"(v));
}

// ---- zero per-launch state ----
__global__ void k_zero(){
    int i = blockIdx.x*256 + threadIdx.x;
    if (i < NSEG)   g_cnt[i] = 0;
    if (i < BB*DD)  g_pooled[i] = 0.f;
}

// ---- CSR build: count messages per destination node ----
__global__ void k_count(const int* __restrict__ a0, const int* __restrict__ a1,
                        const int* __restrict__ pidx){
    int e = blockIdx.x*256 + threadIdx.x;
    if (e >= NEDGE) return;
    int b = e / FF;
    int v0 = a0[e], v1 = a1[e], p = pidx[e];
    bool role = (p == 1);
    int dstf = role ? v0 : v1;
    atomicAdd(&g_cnt[b*SS + dstf], 1);
    if (!role && p != 0) atomicAdd(&g_cnt[b*SS + v0], 1);
}

// ---- exclusive prefix sum over 8192 counts (single block, 1024 thr) ----
__global__ void k_scan(){
    __shared__ int wsum[32];
    int tid = threadIdx.x;
    int base = tid*8;
    int4 c0 = reinterpret_cast<const int4*>(g_cnt)[tid*2];
    int4 c1 = reinterpret_cast<const int4*>(g_cnt)[tid*2+1];
    int cv[8] = {c0.x,c0.y,c0.z,c0.w,c1.x,c1.y,c1.z,c1.w};
    int v[8]; int s = 0;
    #pragma unroll
    for (int i=0;i<8;i++){ v[i]=s; s += cv[i]; }
    int lane = tid & 31, warp = tid >> 5;
    int x = s;
    #pragma unroll
    for (int o=1;o<32;o<<=1){ int y=__shfl_up_sync(0xffffffffu,x,o); if(lane>=o) x+=y; }
    if (lane==31) wsum[warp]=x;
    __syncthreads();
    if (warp==0){
        int w = wsum[lane];
        #pragma unroll
        for (int o=1;o<32;o<<=1){ int y=__shfl_up_sync(0xffffffffu,w,o); if(lane>=o) w+=y; }
        wsum[lane]=w;
    }
    __syncthreads();
    int excl = x - s + (warp ? wsum[warp-1] : 0);
    #pragma unroll
    for (int i=0;i<8;i++){ int o = excl+v[i]; g_off[base+i]=o; g_run[base+i]=o; }
}

// ---- place message descriptors into CSR slots ----
__global__ void k_place(const int* __restrict__ a0, const int* __restrict__ a1,
                        const int* __restrict__ pidx, const int* __restrict__ ridx){
    int e = blockIdx.x*256 + threadIdx.x;
    if (e >= NEDGE) return;
    int b = e / FF;
    int v0=a0[e], v1=a1[e], p=pidx[e];
    bool role = (p==1);
    unsigned descf; int dstf;
    if (role){ dstf=v0; descf=(unsigned)v0 | ((unsigned)(ridx[e]+1)<<10) | ((unsigned)p<<20) | (1u<<23); }
    else     { dstf=v1; descf=(unsigned)v0 | ((unsigned)v1<<10)          | ((unsigned)p<<20); }
    int slot = atomicAdd(&g_run[b*SS+dstf],1);
    g_perm[slot]=descf;
    if (!role && p!=0){
        unsigned descb = (unsigned)v1 | ((unsigned)v0<<10) | ((unsigned)p<<20);
        slot = atomicAdd(&g_run[b*SS+v0],1);
        g_perm[slot]=descb;
    }
}

// ---- 64x64 fp32 GEMM for the small precompute GEMMs (z selects W1 slice) ----
__global__ void k_gemm_pos(const float* __restrict__ A, const float* __restrict__ W1,
                           float* __restrict__ Cb, int M, int N, int K){
    const float* Bm = W1 + (blockIdx.z ? (size_t)2*DD*DH : 0);
    float* C = Cb + (size_t)blockIdx.z * SS*DH;
    __shared__ float As[16][68];
    __shared__ float Bs[16][64];
    int tid = threadIdx.x;
    int bm = blockIdx.y*64, bn = blockIdx.x*64;
    int tx = tid & 15, ty = tid >> 4;
    int la_k = tid & 15, la_m = (tid >> 4)*4;
    int lb_n = tid & 63, lb_k = (tid >> 6)*4;
    float acc[4][4] = {};
    for (int k0=0;k0<K;k0+=16){
        #pragma unroll
        for (int i=0;i<4;i++) As[la_k][la_m+i] = A[(size_t)(bm+la_m+i)*K + k0 + la_k];
        #pragma unroll
        for (int i=0;i<4;i++) Bs[lb_k+i][lb_n] = Bm[(size_t)(k0+lb_k+i)*N + bn + lb_n];
        __syncthreads();
        #pragma unroll
        for (int k=0;k<16;k++){
            float a[4], bv[4];
            #pragma unroll
            for (int i=0;i<4;i++) a[i]=As[k][ty*4+i];
            #pragma unroll
            for (int j=0;j<4;j++) bv[j]=Bs[k][tx*4+j];
            #pragma unroll
            for (int i=0;i<4;i++)
                #pragma unroll
                for (int j=0;j<4;j++) acc[i][j] += a[i]*bv[j];
        }
        __syncthreads();
    }
    #pragma unroll
    for (int i=0;i<4;i++)
        #pragma unroll
        for (int j=0;j<4;j++)
            C[(size_t)(bm+ty*4+i)*N + bn+tx*4+j] = acc[i][j];
}

// ---- big fp32 GEMM: 128x128 tiles, 8x8/thread, double-buffered, FFMA2 ----
// C[M,N] = A[M,K] @ B[K,N]; requires M%128==0, N%128==0, K%16==0
__global__ __launch_bounds__(256)
void k_gemm128(const float* __restrict__ A, const float* __restrict__ B,
               float* __restrict__ C, int M, int N, int K){
    __shared__ float As[2][16][132];   // transposed: As[k][m], row 528B (16B-aligned)
    __shared__ float Bs[2][16][128];
    int tid = threadIdx.x;
    int bm = blockIdx.y*128, bn = blockIdx.x*128;
    int tx = tid & 15, ty = tid >> 4;          // 8x8 tile at (ty*8, tx*8)

    // load mappings (per thread: 2 float4 of A, 2 float4 of B)
    int aidx0 = tid*2, aidx1 = tid*2+1;        // over 512 float4 = 128 rows x 4 kchunks
    int ar0 = aidx0>>2, ac0 = aidx0&3;
    int ar1 = aidx1>>2, ac1 = aidx1&3;
    int br0 = aidx0>>5, bc0 = aidx0&31;        // over 512 float4 = 16 krows x 32 nchunks
    int br1 = aidx1>>5, bc1 = aidx1&31;

    float4 pa0, pa1, pb0, pb1;
    // prefetch tile 0
    pa0 = *reinterpret_cast<const float4*>(&A[(size_t)(bm+ar0)*K + ac0*4]);
    pa1 = *reinterpret_cast<const float4*>(&A[(size_t)(bm+ar1)*K + ac1*4]);
    pb0 = *reinterpret_cast<const float4*>(&B[(size_t)(br0)*N + bn + bc0*4]);
    pb1 = *reinterpret_cast<const float4*>(&B[(size_t)(br1)*N + bn + bc1*4]);

    ull acc2[4][8];
    #pragma unroll
    for (int i=0;i<4;i++)
        #pragma unroll
        for (int j=0;j<8;j++) acc2[i][j]=0ull;

    int buf = 0;
    // store tile 0
    As[0][ac0*4+0][ar0]=pa0.x; As[0][ac0*4+1][ar0]=pa0.y; As[0][ac0*4+2][ar0]=pa0.z; As[0][ac0*4+3][ar0]=pa0.w;
    As[0][ac1*4+0][ar1]=pa1.x; As[0][ac1*4+1][ar1]=pa1.y; As[0][ac1*4+2][ar1]=pa1.z; As[0][ac1*4+3][ar1]=pa1.w;
    *reinterpret_cast<float4*>(&Bs[0][br0][bc0*4]) = pb0;
    *reinterpret_cast<float4*>(&Bs[0][br1][bc1*4]) = pb1;
    __syncthreads();

    int ktiles = K/16;
    for (int kt=0; kt<ktiles; kt++){
        bool more = (kt+1 < ktiles);
        if (more){
            int kk = (kt+1)*16;
            pa0 = *reinterpret_cast<const float4*>(&A[(size_t)(bm+ar0)*K + kk + ac0*4]);
            pa1 = *reinterpret_cast<const float4*>(&A[(size_t)(bm+ar1)*K + kk + ac1*4]);
            pb0 = *reinterpret_cast<const float4*>(&B[(size_t)(kk+br0)*N + bn + bc0*4]);
            pb1 = *reinterpret_cast<const float4*>(&B[(size_t)(kk+br1)*N + bn + bc1*4]);
        }
        #pragma unroll
        for (int k=0;k<16;k++){
            const ull* a64 = reinterpret_cast<const ull*>(&As[buf][k][ty*8]);
            ull ap0=a64[0], ap1=a64[1], ap2=a64[2], ap3=a64[3];
            const float4* b4 = reinterpret_cast<const float4*>(&Bs[buf][k][tx*8]);
            float4 b0 = b4[0], b1 = b4[1];
            float bv[8] = {b0.x,b0.y,b0.z,b0.w,b1.x,b1.y,b1.z,b1.w};
            #pragma unroll
            for (int j=0;j<8;j++){
                ull bb = pack2(bv[j]);
                ffma2(acc2[0][j], ap0, bb);
                ffma2(acc2[1][j], ap1, bb);
                ffma2(acc2[2][j], ap2, bb);
                ffma2(acc2[3][j], ap3, bb);
            }
        }
        if (more){
            buf ^= 1;
            As[buf][ac0*4+0][ar0]=pa0.x; As[buf][ac0*4+1][ar0]=pa0.y; As[buf][ac0*4+2][ar0]=pa0.z; As[buf][ac0*4+3][ar0]=pa0.w;
            As[buf][ac1*4+0][ar1]=pa1.x; As[buf][ac1*4+1][ar1]=pa1.y; As[buf][ac1*4+2][ar1]=pa1.z; As[buf][ac1*4+3][ar1]=pa1.w;
            *reinterpret_cast<float4*>(&Bs[buf][br0][bc0*4]) = pb0;
            *reinterpret_cast<float4*>(&Bs[buf][br1][bc1*4]) = pb1;
            __syncthreads();
        }
    }

    // epilogue: unpack acc2 pairs (rows 2*i2, 2*i2+1) and store with STG.128
    #pragma unroll
    for (int i2=0;i2<4;i2++){
        float lo[8], hi[8];
        #pragma unroll
        for (int j=0;j<8;j++) unpack2(lo[j], hi[j], acc2[i2][j]);
        size_t r0 = (size_t)(bm + ty*8 + i2*2)*N + bn + tx*8;
        size_t r1 = r0 + N;
        reinterpret_cast<float4*>(&C[r0])[0] = make_float4(lo[0],lo[1],lo[2],lo[3]);
        reinterpret_cast<float4*>(&C[r0])[1] = make_float4(lo[4],lo[5],lo[6],lo[7]);
        reinterpret_cast<float4*>(&C[r1])[0] = make_float4(hi[0],hi[1],hi[2],hi[3]);
        reinterpret_cast<float4*>(&C[r1])[1] = make_float4(hi[4],hi[5],hi[6],hi[7]);
    }
}

// ---- tiny GEMM for 8-row tables: grid 16 (0-7 pred, 8-15 role) ----
__global__ void k_smallmm(const float* __restrict__ pre, const float* __restrict__ rol,
                          const float* __restrict__ W1){
    __shared__ float a[DD];
    int blk = blockIdx.x, j = threadIdx.x;   // 512 threads
    const float* A; const float* W; float* C; int r;
    if (blk < 8){ A=pre; W=W1+DD*DH;   C=g_Eb; r=blk; }
    else        { A=rol; W=W1+2*DD*DH; C=g_Rc; r=blk-8; }
    if (j < DD) a[j] = A[r*DD + j];
    __syncthreads();
    float s = 0.f;
    for (int k=0;k<DD;k++) s += a[k]*W[(size_t)k*DH + j];
    C[r*DH + j] = s;
}

// ---- per-node gather: H[node] = sum over msgs of gelu(Pa+T+Eb+b1) ----
__global__ void k_gather(const float* __restrict__ b1){
    int node = blockIdx.x;
    int tid = threadIdx.x;                 // 128 threads, 4 floats each
    int start = g_off[node];
    int cnt = g_cnt[node];
    float4 b1v = reinterpret_cast<const float4*>(b1)[tid];
    float4 acc = make_float4(0.f,0.f,0.f,0.f);
    const float4* PA = reinterpret_cast<const float4*>(g_P);
    const float4* PC = PA + SS*DH/4;
    const float4* EB = reinterpret_cast<const float4*>(g_Eb);
    const float4* RC = reinterpret_cast<const float4*>(g_Rc);
    for (int m=0;m<cnt;m++){
        unsigned d = g_perm[start+m];
        int iA = d & 1023, iC = (d>>10)&1023, p = (d>>20)&7;
        const float4* T = (d & (1u<<23)) ? RC : PC;
        float4 a = PA[iA*128 + tid];
        float4 c = T [iC*128 + tid];
        float4 e = EB[p *128 + tid];
        acc.x += gelu_f(a.x+c.x+e.x+b1v.x);
        acc.y += gelu_f(a.y+c.y+e.y+b1v.y);
        acc.z += gelu_f(a.z+c.z+e.z+b1v.z);
        acc.w += gelu_f(a.w+c.w+e.w+b1v.w);
    }
    reinterpret_cast<float4*>(g_H)[node*128 + tid] = acc;
}

// ---- x = pos + agg + cnt*b2 ; layernorm ; accumulate pooled sums ----
__global__ void k_ln(const float* __restrict__ pos, const float* __restrict__ b2,
                     const float* __restrict__ lng, const float* __restrict__ lnb){
    __shared__ float sp[DD];
    int bIdx = blockIdx.y;
    int r0 = blockIdx.x*64;
    int tid = threadIdx.x;                 // 256 = 8 warps
    int warp = tid>>5, lane = tid&31;
    float accp[8];
    #pragma unroll
    for (int i=0;i<8;i++) accp[i]=0.f;
    for (int rr=warp; rr<64; rr+=8){
        int s = r0+rr;
        int seg = bIdx*SS + s;
        float cntf = (float)g_cnt[seg];
        float x[8]; float sum=0.f;
        #pragma unroll
        for (int i=0;i<8;i++){
            int j = lane + 32*i;
            x[i] = pos[s*DD+j] + g_agg[(size_t)seg*DD+j] + cntf*b2[j];
            sum += x[i];
        }
        #pragma unroll
        for (int o=16;o;o>>=1) sum += __shfl_xor_sync(0xffffffffu,sum,o);
        float mu = sum*(1.0f/DD);
        float vs=0.f;
        #pragma unroll
        for (int i=0;i<8;i++){ float d2 = x[i]-mu; vs += d2*d2; }
        #pragma unroll
        for (int o=16;o;o>>=1) vs += __shfl_xor_sync(0xffffffffu,vs,o);
        float inv = rsqrtf(vs*(1.0f/DD)+1e-5f);
        #pragma unroll
        for (int i=0;i<8;i++){
            int j = lane+32*i;
            accp[i] += (x[i]-mu)*inv*lng[j] + lnb[j];
        }
    }
    if (tid < DD) sp[tid]=0.f;
    __syncthreads();
    #pragma unroll
    for (int i=0;i<8;i++) atomicAdd(&sp[lane+32*i], accp[i]);
    __syncthreads();
    if (tid < DD) atomicAdd(&g_pooled[bIdx*DD+tid], sp[tid]);
}

// ---- final tiny MLP ----
__global__ void k_final(const float* __restrict__ Wl1, const float* __restrict__ bl1,
                        const float* __restrict__ Wl2, const float* __restrict__ bl2,
                        float* __restrict__ out){
    __shared__ float pp[DD];
    __shared__ float hh[DLAT];
    int b = blockIdx.x, j = threadIdx.x;   // 512 threads
    if (j < DD) pp[j] = g_pooled[b*DD+j]*(1.0f/SS);
    __syncthreads();
    float s = bl1[j];
    for (int k=0;k<DD;k++) s += pp[k]*Wl1[(size_t)k*DLAT+j];
    hh[j] = gelu_f(s);
    __syncthreads();
    float o = bl2[j];
    for (int k=0;k<DLAT;k++) o += hh[k]*Wl2[(size_t)k*DLAT+j];
    out[b*DLAT+j] = o;
}

extern "C" void kernel_launch(void* const* d_in, const int* in_sizes, int n_in,
                              void* d_out, int out_size){
    const int*   a0   = (const int*)d_in[0];
    const int*   a1   = (const int*)d_in[1];
    const int*   pidx = (const int*)d_in[2];
    const int*   ridx = (const int*)d_in[3];
    const float* pos  = (const float*)d_in[5];
    const float* pre  = (const float*)d_in[6];
    const float* rol  = (const float*)d_in[7];
    const float* W1   = (const float*)d_in[8];
    const float* b1   = (const float*)d_in[9];
    const float* W2   = (const float*)d_in[10];
    const float* b2   = (const float*)d_in[11];
    const float* lng  = (const float*)d_in[12];
    const float* lnb  = (const float*)d_in[13];
    const float* Wl1  = (const float*)d_in[14];
    const float* bl1  = (const float*)d_in[15];
    const float* Wl2  = (const float*)d_in[16];
    const float* bl2  = (const float*)d_in[17];
    float* out = (float*)d_out;

    float *pP, *pH, *pAgg;
    cudaGetSymbolAddress((void**)&pP,   g_P);
    cudaGetSymbolAddress((void**)&pH,   g_H);
    cudaGetSymbolAddress((void**)&pAgg, g_agg);

    k_zero<<<32,256>>>();
    k_count<<<NEDGE/256,256>>>(a0,a1,pidx);
    k_scan<<<1,1024>>>();
    k_place<<<NEDGE/256,256>>>(a0,a1,pidx,ridx);

    // precompute tables: pos@W1a and pos@W1c in one launch (z=2)
    k_gemm_pos<<<dim3(DH/64, SS/64, 2),256>>>(pos, W1, pP, SS, DH, DD);
    k_smallmm<<<16,512>>>(pre, rol, W1);

    // per-node hidden accumulation (atomic-free gather)
    k_gather<<<NSEG,128>>>(b1);

    // agg = H @ W2  (FFMA2 128x128 kernel)
    k_gemm128<<<dim3(DD/128, NSEG/128),256>>>(pH, W2, pAgg, NSEG, DD, DH);

    // layernorm + pooling, then final MLP
    k_ln<<<dim3(SS/64,BB),256>>>(pos, b2, lng, lnb);
    k_final<<<BB,512>>>(Wl1,bl1,Wl2,bl2,out);
}